// round 17
// baseline (speedup 1.0000x reference)
#include <cuda_runtime.h>
#include <cstdint>

#define MM 512
#define NN 1024
#define WR 16
#define BB 4096
#define BPB 16           // batches per block (2 warps; 8 lanes per batch-pair group)
#define STRIDE 1028      // padded floats per batch row in smem

#define ABSM 0x7FFFFFFFu
#define SGNM 0x80000000u
#define FULL 0xFFFFFFFFu

// Split c2v state (32 MB total -> fully L2-resident):
//  g_m[cn*BB + batch]          = {m1c bits, m2c bits}  (8 B, written by li==0)
//  g_s[(cn*BB + batch)*8 + li] = flip_lo | flip_hi<<1 | eq_lo<<2 | eq_hi<<3 (1 B)
__device__ uint2 g_m[MM * BB];
__device__ unsigned char g_s[MM * BB * 8];

// Unpack one batch's two edges from split state (off the critical chain).
#define UNPACK(SEL, MMV, CLO, CHI) do {                                      \
    const unsigned alo_ = ((SEL) & 4u) ? (MMV).y : (MMV).x;                  \
    const unsigned ahi_ = ((SEL) & 8u) ? (MMV).y : (MMV).x;                  \
    CLO = __uint_as_float(alo_ | ((SEL) << 31));                             \
    CHI = __uint_as_float(ahi_ | (((SEL) << 30) & SGNM));                    \
} while (0)

// Prefetch slot S for global step T (both batches of the pair).
#define PREFETCH(S, T) do {                                                  \
    cn##S  = __ldg(&cn_order[tm]); if (++tm == MM) tm = 0;                   \
    ilo##S = __ldg(&H[cn##S * WR + li]);                                     \
    ihi##S = __ldg(&H[cn##S * WR + li + 8]);                                 \
    if ((T) < MM) {                                                          \
        cloa##S = 0.0f; chia##S = 0.0f; clob##S = 0.0f; chib##S = 0.0f;      \
    } else {                                                                 \
        const unsigned sela = (unsigned)g_s[(cn##S * BB + ba) * 8 + li];     \
        const unsigned selb = (unsigned)g_s[(cn##S * BB + bb) * 8 + li];     \
        const uint2 mma = g_m[cn##S * BB + ba];                              \
        const uint2 mmb = g_m[cn##S * BB + bb];                              \
        UNPACK(sela, mma, cloa##S, chia##S);                                 \
        UNPACK(selb, mmb, clob##S, chib##S);                                 \
    }                                                                        \
} while (0)

// One check-node update for TWO independent batches, chains interleaved.
#define STEP(S) do {                                                         \
    const float tloa = vna[ilo##S] - cloa##S;                                \
    const float tlob = vnb[ilo##S] - clob##S;                                \
    const float thia = vna[ihi##S] - chia##S;                                \
    const float thib = vnb[ihi##S] - chib##S;                                \
    const unsigned uloa = __float_as_uint(tloa);                             \
    const unsigned ulob = __float_as_uint(tlob);                             \
    const unsigned uhia = __float_as_uint(thia);                             \
    const unsigned uhib = __float_as_uint(thib);                             \
    const float aloa = __uint_as_float(uloa & ABSM);                         \
    const float alob = __uint_as_float(ulob & ABSM);                         \
    const float ahia = __uint_as_float(uhia & ABSM);                         \
    const float ahib = __uint_as_float(uhib & ABSM);                         \
    const unsigned bxa = __ballot_sync(FULL, ((uloa ^ uhia) & SGNM) != 0u);  \
    const unsigned bxb = __ballot_sync(FULL, ((ulob ^ uhib) & SGNM) != 0u);  \
    float m1a = fminf(aloa, ahia), m2a = fmaxf(aloa, ahia);                  \
    float m1b = fminf(alob, ahib), m2b = fmaxf(alob, ahib);                  \
    {   const float p1a = __shfl_xor_sync(FULL, m1a, 1);                     \
        const float p2a = __shfl_xor_sync(FULL, m2a, 1);                     \
        const float p1b = __shfl_xor_sync(FULL, m1b, 1);                     \
        const float p2b = __shfl_xor_sync(FULL, m2b, 1);                     \
        m2a = fminf(fmaxf(m1a, p1a), fminf(m2a, p2a)); m1a = fminf(m1a, p1a);\
        m2b = fminf(fmaxf(m1b, p1b), fminf(m2b, p2b)); m1b = fminf(m1b, p1b);}\
    {   const float p1a = __shfl_xor_sync(FULL, m1a, 2);                     \
        const float p2a = __shfl_xor_sync(FULL, m2a, 2);                     \
        const float p1b = __shfl_xor_sync(FULL, m1b, 2);                     \
        const float p2b = __shfl_xor_sync(FULL, m2b, 2);                     \
        m2a = fminf(fmaxf(m1a, p1a), fminf(m2a, p2a)); m1a = fminf(m1a, p1a);\
        m2b = fminf(fmaxf(m1b, p1b), fminf(m2b, p2b)); m1b = fminf(m1b, p1b);}\
    {   const float p1a = __shfl_xor_sync(FULL, m1a, 4);                     \
        const float p2a = __shfl_xor_sync(FULL, m2a, 4);                     \
        const float p1b = __shfl_xor_sync(FULL, m1b, 4);                     \
        const float p2b = __shfl_xor_sync(FULL, m2b, 4);                     \
        m2a = fminf(fmaxf(m1a, p1a), fminf(m2a, p2a)); m1a = fminf(m1a, p1a);\
        m2b = fminf(fmaxf(m1b, p1b), fminf(m2b, p2b)); m1b = fminf(m1b, p1b);}\
    const unsigned para31 = ((unsigned)__popc((bxa >> sh) & 0xFFu) & 1u) << 31; \
    const unsigned parb31 = ((unsigned)__popc((bxb >> sh) & 0xFFu) & 1u) << 31; \
    const float m1ca = fminf(m1a, 20.0f), m2ca = fminf(m2a, 20.0f);          \
    const float m1cb = fminf(m1b, 20.0f), m2cb = fminf(m2b, 20.0f);          \
    const unsigned eqloa = (aloa == m1a) ? 1u : 0u;                          \
    const unsigned eqhia = (ahia == m1a) ? 1u : 0u;                          \
    const unsigned eqlob = (alob == m1b) ? 1u : 0u;                          \
    const unsigned eqhib = (ahib == m1b) ? 1u : 0u;                          \
    const float cwloa = __uint_as_float(__float_as_uint(eqloa ? m2ca : m1ca) \
                                        | ((para31 ^ uloa) & SGNM));         \
    const float cwhia = __uint_as_float(__float_as_uint(eqhia ? m2ca : m1ca) \
                                        | ((para31 ^ uhia) & SGNM));         \
    const float cwlob = __uint_as_float(__float_as_uint(eqlob ? m2cb : m1cb) \
                                        | ((parb31 ^ ulob) & SGNM));         \
    const float cwhib = __uint_as_float(__float_as_uint(eqhib ? m2cb : m1cb) \
                                        | ((parb31 ^ uhib) & SGNM));         \
    vna[ilo##S] = tloa + cwloa;                                              \
    vnb[ilo##S] = tlob + cwlob;                                              \
    vna[ihi##S] = thia + cwhia;                                              \
    vnb[ihi##S] = thib + cwhib;                                              \
    g_s[(cn##S * BB + ba) * 8 + li] = (unsigned char)(                       \
        (__float_as_uint(cwloa) >> 31) | ((__float_as_uint(cwhia) >> 31) << 1) \
        | (eqloa << 2) | (eqhia << 3));                                      \
    g_s[(cn##S * BB + bb) * 8 + li] = (unsigned char)(                       \
        (__float_as_uint(cwlob) >> 31) | ((__float_as_uint(cwhib) >> 31) << 1) \
        | (eqlob << 2) | (eqhib << 3));                                      \
    if (li == 0) {                                                           \
        g_m[cn##S * BB + ba] =                                               \
            make_uint2(__float_as_uint(m1ca), __float_as_uint(m2ca));        \
        g_m[cn##S * BB + bb] =                                               \
            make_uint2(__float_as_uint(m1cb), __float_as_uint(m2cb));        \
    }                                                                        \
    __syncwarp();                                                            \
} while (0)

__global__ __launch_bounds__(64)
void ldpc_layered_ms_kernel(const float* __restrict__ llr,
                            const int*   __restrict__ H,
                            const int*   __restrict__ iters_p,
                            const int*   __restrict__ cn_order,
                            float*       __restrict__ out)
{
    __shared__ float sh_vn[BPB * STRIDE];       // 16 * 1028 * 4 B = 64.25 KB

    const int tid   = threadIdx.x;              // 0..63
    const int lane  = tid & 31;
    const int li    = lane & 7;                 // lane within 8-lane group
    const int sh    = lane & 24;                // group's bit offset in ballots
    const int g     = tid >> 3;                 // group 0..7
    const int ba    = blockIdx.x * BPB + g * 2; // batch A
    const int bb    = ba + 1;                   // batch B

    float* vna = sh_vn + (g * 2 + 0) * STRIDE;
    float* vnb = sh_vn + (g * 2 + 1) * STRIDE;

    // Load channel LLRs for both batches (float4 per lane).
    {
        const float4* sa = (const float4*)(llr + (size_t)ba * NN);
        const float4* sb = (const float4*)(llr + (size_t)bb * NN);
        #pragma unroll 4
        for (int k = li; k < NN / 4; k += 8) {
            const float4 va = __ldg(sa + k);
            const float4 vb = __ldg(sb + k);
            vna[4*k+0] = va.x; vna[4*k+1] = va.y; vna[4*k+2] = va.z; vna[4*k+3] = va.w;
            vnb[4*k+0] = vb.x; vnb[4*k+1] = vb.y; vnb[4*k+2] = vb.z; vnb[4*k+3] = vb.w;
        }
    }
    __syncwarp();

    const int iters = *iters_p;
    const int total = iters * MM;               // 2560, even

    // ---- 2-deep software pipeline ----
    int cnA, cnB, iloA, ihiA, iloB, ihiB;
    float cloaA, chiaA, clobA, chibA;
    float cloaB, chiaB, clobB, chibB;
    int tm = 0;
    PREFETCH(A, 0);
    PREFETCH(B, 1);

    for (int t = 0; t < total; t += 2) {
        STEP(A); PREFETCH(A, t + 2);   // cn distinct within window: safe vs stores
        STEP(B); PREFETCH(B, t + 3);
    }

    // Hard decision output for both batches.
    {
        float4* da = (float4*)(out + (size_t)ba * NN);
        float4* db = (float4*)(out + (size_t)bb * NN);
        #pragma unroll 4
        for (int k = li; k < NN / 4; k += 8) {
            float4 ra, rb;
            ra.x = (vna[4*k+0] < 0.f) ? 1.f : 0.f;
            ra.y = (vna[4*k+1] < 0.f) ? 1.f : 0.f;
            ra.z = (vna[4*k+2] < 0.f) ? 1.f : 0.f;
            ra.w = (vna[4*k+3] < 0.f) ? 1.f : 0.f;
            rb.x = (vnb[4*k+0] < 0.f) ? 1.f : 0.f;
            rb.y = (vnb[4*k+1] < 0.f) ? 1.f : 0.f;
            rb.z = (vnb[4*k+2] < 0.f) ? 1.f : 0.f;
            rb.w = (vnb[4*k+3] < 0.f) ? 1.f : 0.f;
            da[k] = ra;
            db[k] = rb;
        }
    }
}

extern "C" void kernel_launch(void* const* d_in, const int* in_sizes, int n_in,
                              void* d_out, int out_size)
{
    const float* llr      = (const float*)d_in[0];   // channel_llr [4096,1024] f32
    const int*   H        = (const int*)  d_in[1];   // H_compact   [512,16]    i32
    const int*   iters_p  = (const int*)  d_in[2];   // iters scalar
    const int*   cn_order = (const int*)  d_in[3];   // cn_order    [512]       i32
    float*       out      = (float*)d_out;

    (void)in_sizes; (void)n_in; (void)out_size;

    ldpc_layered_ms_kernel<<<BB / BPB, 64>>>(llr, H, iters_p, cn_order, out);
}